// round 5
// baseline (speedup 1.0000x reference)
#include <cuda_runtime.h>
#include <math.h>

// Problem constants
#define T_STEPS 256
#define BSZ     64
#define DIM     1024
#define N3      (3 * DIM)          // 3072
#define M_TOTAL (T_STEPS * BSZ)    // 16384
#define NCTA    128
#define NTHR    256

typedef unsigned long long ull;

// Scratch (__device__ globals; allocation-free rule)
__device__ float g_xproj[(size_t)M_TOTAL * N3];     // [T,B,3D] ~192 MiB
__device__ float g_part[4 * BSZ * N3];              // split-K partials
__device__ float g_heff[BSZ * DIM];                 // reset-applied h for current step
__device__ int   g_dones_is_byte;
__device__ unsigned g_bar_count;
__device__ unsigned g_bar_epoch;

// ---------------- packed f32x2 helpers ----------------
__device__ __forceinline__ ull ffma2(ull a, ull b, ull c) {
    ull d;
    asm("fma.rn.f32x2 %0, %1, %2, %3;" : "=l"(d) : "l"(a), "l"(b), "l"(c));
    return d;
}
__device__ __forceinline__ float2 unpack2(ull v) {
    float2 r;
    asm("mov.b64 {%0, %1}, %2;" : "=f"(r.x), "=f"(r.y) : "l"(v));
    return r;
}

// ---------------- dones dtype probe ----------------
__global__ void detect_dones_kernel(const unsigned char* __restrict__ p) {
    int nz = 0;
    for (int i = 0; i < 256; i++)
        if ((i & 3) != 0 && p[i] != 0) nz++;
    g_dones_is_byte = (nz > 0) ? 1 : 0;
}
__device__ __forceinline__ bool read_done(const void* dones, int idx, int is_byte) {
    if (is_byte) return ((const unsigned char*)dones)[idx] != 0;
    return ((const int*)dones)[idx] != 0;
}

// ---------------------------------------------------------------------------
// Phase 1: x_proj = ins @ W_i + b_i   (M=16384, K=1024, N=3072)
// BM=128, BN=64, BK=16. A stored m-DUPLICATED in SMEM so the FFMA2 a-operand
// (a,a) comes straight from LDS.128 (no packs). Double-buffered, 1 sync/tile.
// ---------------------------------------------------------------------------
#define BM1 128
#define BN1 64
#define BK1 16
#define NTILE1 (DIM / BK1)    // 64 k-tiles

__global__ __launch_bounds__(256) void gemm_xproj_kernel(
    const float* __restrict__ A, const float* __restrict__ W,
    const float* __restrict__ bias)
{
    // As: [2][BK1][2*BM1] (m-duplicated)  2*16*256*4 = 64 KB
    // Bs: [2][BK1][BN1]                   2*16*64*4  =  8 KB
    __shared__ __align__(16) float As[2][BK1][2 * BM1];
    __shared__ __align__(16) float Bs[2][BK1][BN1];

    const int K = DIM, N = N3;
    const int bn = blockIdx.x, bm = blockIdx.y;
    const int tid = threadIdx.x;
    const int tx = tid & 15;    // 16 col-groups of 4 n
    const int ty = tid >> 4;    // 16 row-groups of 8 m

    ull acc[8][2];
#pragma unroll
    for (int i = 0; i < 8; i++) { acc[i][0] = 0ull; acc[i][1] = 0ull; }

    const float* Ab = A + (size_t)bm * BM1 * K;
    const float* Wb = W + (size_t)bn * BN1;

    // Per-thread load coords (A: 2 float4; B: 1 float4)
    const int ar0 = (tid * 4) >> 4;            // m row for v=0
    const int ac0 = (tid * 4) & 15;            // k col
    const int ar1 = ((tid + 256) * 4) >> 4;
    const int ac1 = ((tid + 256) * 4) & 15;
    const int br = (tid * 4) >> 6;             // k row
    const int bc = (tid * 4) & 63;             // n col

    float4 pa0, pa1, pb;

    // prologue: load tile 0 into regs, store to buf 0
    pa0 = *(const float4*)(Ab + (size_t)ar0 * K + ac0);
    pa1 = *(const float4*)(Ab + (size_t)ar1 * K + ac1);
    pb  = *(const float4*)(Wb + (size_t)br * N + bc);
    {
        float4 d;
        d.x = pa0.x; d.y = pa0.x; d.z = pa0.y; d.w = pa0.y;
        // store duplicated: As[k][2m], As[k][2m+1]
        As[0][ac0 + 0][2 * ar0] = pa0.x; As[0][ac0 + 0][2 * ar0 + 1] = pa0.x;
        As[0][ac0 + 1][2 * ar0] = pa0.y; As[0][ac0 + 1][2 * ar0 + 1] = pa0.y;
        As[0][ac0 + 2][2 * ar0] = pa0.z; As[0][ac0 + 2][2 * ar0 + 1] = pa0.z;
        As[0][ac0 + 3][2 * ar0] = pa0.w; As[0][ac0 + 3][2 * ar0 + 1] = pa0.w;
        As[0][ac1 + 0][2 * ar1] = pa1.x; As[0][ac1 + 0][2 * ar1 + 1] = pa1.x;
        As[0][ac1 + 1][2 * ar1] = pa1.y; As[0][ac1 + 1][2 * ar1 + 1] = pa1.y;
        As[0][ac1 + 2][2 * ar1] = pa1.z; As[0][ac1 + 2][2 * ar1 + 1] = pa1.z;
        As[0][ac1 + 3][2 * ar1] = pa1.w; As[0][ac1 + 3][2 * ar1 + 1] = pa1.w;
        *(float4*)&Bs[0][br][bc] = pb;
        (void)d;
    }
    __syncthreads();

    for (int t = 0; t < NTILE1; t++) {
        const int cur = t & 1, nxt = cur ^ 1;
        // issue next tile's loads early (hide LDG latency under compute)
        if (t + 1 < NTILE1) {
            int k0 = (t + 1) * BK1;
            pa0 = *(const float4*)(Ab + (size_t)ar0 * K + k0 + ac0);
            pa1 = *(const float4*)(Ab + (size_t)ar1 * K + k0 + ac1);
            pb  = *(const float4*)(Wb + (size_t)(k0 + br) * N + bc);
        }

#pragma unroll
        for (int kk = 0; kk < BK1; kk++) {
            // a: 8 duplicated m-values = 4 LDS.128 (each = 2 ull pairs)
            ull a0 = *(const ull*)&As[cur][kk][2 * (ty * 8) + 0];
            ull a1 = *(const ull*)&As[cur][kk][2 * (ty * 8) + 2];
            ull a2 = *(const ull*)&As[cur][kk][2 * (ty * 8) + 4];
            ull a3 = *(const ull*)&As[cur][kk][2 * (ty * 8) + 6];
            ull a4 = *(const ull*)&As[cur][kk][2 * (ty * 8) + 8];
            ull a5 = *(const ull*)&As[cur][kk][2 * (ty * 8) + 10];
            ull a6 = *(const ull*)&As[cur][kk][2 * (ty * 8) + 12];
            ull a7 = *(const ull*)&As[cur][kk][2 * (ty * 8) + 14];
            // b: 4 n-values = 2 distinct-pair ulls (1 LDS.128)
            ull b0 = *(const ull*)&Bs[cur][kk][tx * 4];
            ull b1 = *(const ull*)&Bs[cur][kk][tx * 4 + 2];
            acc[0][0] = ffma2(a0, b0, acc[0][0]); acc[0][1] = ffma2(a0, b1, acc[0][1]);
            acc[1][0] = ffma2(a1, b0, acc[1][0]); acc[1][1] = ffma2(a1, b1, acc[1][1]);
            acc[2][0] = ffma2(a2, b0, acc[2][0]); acc[2][1] = ffma2(a2, b1, acc[2][1]);
            acc[3][0] = ffma2(a3, b0, acc[3][0]); acc[3][1] = ffma2(a3, b1, acc[3][1]);
            acc[4][0] = ffma2(a4, b0, acc[4][0]); acc[4][1] = ffma2(a4, b1, acc[4][1]);
            acc[5][0] = ffma2(a5, b0, acc[5][0]); acc[5][1] = ffma2(a5, b1, acc[5][1]);
            acc[6][0] = ffma2(a6, b0, acc[6][0]); acc[6][1] = ffma2(a6, b1, acc[6][1]);
            acc[7][0] = ffma2(a7, b0, acc[7][0]); acc[7][1] = ffma2(a7, b1, acc[7][1]);
        }

        if (t + 1 < NTILE1) {
            As[nxt][ac0 + 0][2 * ar0] = pa0.x; As[nxt][ac0 + 0][2 * ar0 + 1] = pa0.x;
            As[nxt][ac0 + 1][2 * ar0] = pa0.y; As[nxt][ac0 + 1][2 * ar0 + 1] = pa0.y;
            As[nxt][ac0 + 2][2 * ar0] = pa0.z; As[nxt][ac0 + 2][2 * ar0 + 1] = pa0.z;
            As[nxt][ac0 + 3][2 * ar0] = pa0.w; As[nxt][ac0 + 3][2 * ar0 + 1] = pa0.w;
            As[nxt][ac1 + 0][2 * ar1] = pa1.x; As[nxt][ac1 + 0][2 * ar1 + 1] = pa1.x;
            As[nxt][ac1 + 1][2 * ar1] = pa1.y; As[nxt][ac1 + 1][2 * ar1 + 1] = pa1.y;
            As[nxt][ac1 + 2][2 * ar1] = pa1.z; As[nxt][ac1 + 2][2 * ar1 + 1] = pa1.z;
            As[nxt][ac1 + 3][2 * ar1] = pa1.w; As[nxt][ac1 + 3][2 * ar1 + 1] = pa1.w;
            *(float4*)&Bs[nxt][br][bc] = pb;
        }
        __syncthreads();
    }

    int n0 = bn * BN1 + tx * 4;
    float4 bv = *(const float4*)&bias[n0];
#pragma unroll
    for (int i = 0; i < 8; i++) {
        int m = bm * BM1 + ty * 8 + i;
        float2 v0 = unpack2(acc[i][0]);
        float2 v1 = unpack2(acc[i][1]);
        float4 o;
        o.x = v0.x + bv.x; o.y = v0.y + bv.y;
        o.z = v1.x + bv.z; o.w = v1.y + bv.w;
        *(float4*)&g_xproj[(size_t)m * N + n0] = o;
    }
}

// ---------------------------------------------------------------------------
// Persistent scan kernel (128 CTAs, 2 grid barriers/step).
// Hs now stored k-DUPLICATED so the FFMA2 a-operand needs no packs.
// ---------------------------------------------------------------------------
__device__ __forceinline__ void grid_barrier(unsigned* s_epoch, bool last) {
    __threadfence();
    __syncthreads();
    if (threadIdx.x == 0) {
        unsigned my = *s_epoch;
        unsigned prev = atomicAdd(&g_bar_count, 1u);
        if (prev == NCTA - 1) {
            g_bar_count = 0;
            __threadfence();
            atomicExch(&g_bar_epoch, last ? 0u : (my + 1u));
        } else {
            volatile unsigned* ep = &g_bar_epoch;
            while (*ep == my) { __nanosleep(64); }
            __threadfence();
        }
        *s_epoch = my + 1u;
    }
    __syncthreads();
}

// Bs: 256k x 96n = 96 KB;  Hs: 64b x 512 (k duplicated) = 128 KB;  total 224 KB
#define SCAN_SMEM ((256 * 96 + BSZ * 512) * 4)

__global__ __launch_bounds__(NTHR, 1) void scan_kernel(
    const float* __restrict__ hiddens,
    const void*  __restrict__ dones,
    const float* __restrict__ init_carry,
    const float* __restrict__ W_h,
    const float* __restrict__ b_hn,
    float* __restrict__ out)
{
    extern __shared__ float smem[];
    float* Bs = smem;                    // [256][96]
    float* Hs = smem + 256 * 96;         // [64][512] duplicated over k
    __shared__ unsigned s_epoch;

    const int tid = threadIdx.x;
    const int cta = blockIdx.x;
    const int bn = cta & 31;
    const int kidx = cta >> 5;
    const int kbase = kidx * 256;
    const int tx = tid & 15;
    const int ty = tid >> 4;
    const int is_byte = g_dones_is_byte;
    float* ys = out + (size_t)BSZ * DIM;

    if (tid == 0) s_epoch = 0;

    // W_h slice -> SMEM once
    for (int i = tid; i < 256 * 24; i += NTHR) {
        int k = i / 24, c4 = (i % 24) * 4;
        *(float4*)&Bs[k * 96 + c4] =
            *(const float4*)&W_h[(size_t)(kbase + k) * N3 + bn * 96 + c4];
    }

    // initial h_eff (t=0 reset applied)
    {
        int e = cta * 512 + tid * 2;
        int b = e >> 10, d = e & 1023;
        bool dn = read_done(dones, b, is_byte);
        const float* src = dn ? (hiddens + (size_t)b * DIM)
                              : (init_carry + (size_t)b * DIM);
        float2 v = *(const float2*)&src[d];
        *(float2*)&g_heff[b * DIM + d] = v;
    }
    grid_barrier(&s_epoch, false);

    for (int t = 0; t < T_STEPS; t++) {
        // ---- stage h chunk, duplicated over k ----
        for (int i = tid; i < BSZ * 64; i += NTHR) {
            int b = i >> 6;
            int c4 = (i & 63) * 4;
            float4 v = __ldcg((const float4*)&g_heff[b * DIM + kbase + c4]);
            float4 d0, d1;
            d0.x = v.x; d0.y = v.x; d0.z = v.y; d0.w = v.y;
            d1.x = v.z; d1.y = v.z; d1.z = v.w; d1.w = v.w;
            *(float4*)&Hs[b * 512 + 2 * c4 + 0] = d0;
            *(float4*)&Hs[b * 512 + 2 * c4 + 4] = d1;
        }
        __syncthreads();

        ull acc[4][3];
#pragma unroll
        for (int i = 0; i < 4; i++)
#pragma unroll
            for (int j = 0; j < 3; j++) acc[i][j] = 0ull;

        const float* hrow0 = Hs + (ty * 4 + 0) * 512;
        const float* hrow1 = Hs + (ty * 4 + 1) * 512;
        const float* hrow2 = Hs + (ty * 4 + 2) * 512;
        const float* hrow3 = Hs + (ty * 4 + 3) * 512;
        const float* bcol = Bs + tx * 6;

#pragma unroll 8
        for (int k = 0; k < 256; k++) {
            ull b0 = *(const ull*)&bcol[k * 96 + 0];
            ull b1 = *(const ull*)&bcol[k * 96 + 2];
            ull b2 = *(const ull*)&bcol[k * 96 + 4];
            ull a0 = *(const ull*)&hrow0[2 * k];
            ull a1 = *(const ull*)&hrow1[2 * k];
            ull a2 = *(const ull*)&hrow2[2 * k];
            ull a3 = *(const ull*)&hrow3[2 * k];
            acc[0][0] = ffma2(a0, b0, acc[0][0]);
            acc[0][1] = ffma2(a0, b1, acc[0][1]);
            acc[0][2] = ffma2(a0, b2, acc[0][2]);
            acc[1][0] = ffma2(a1, b0, acc[1][0]);
            acc[1][1] = ffma2(a1, b1, acc[1][1]);
            acc[1][2] = ffma2(a1, b2, acc[1][2]);
            acc[2][0] = ffma2(a2, b0, acc[2][0]);
            acc[2][1] = ffma2(a2, b1, acc[2][1]);
            acc[2][2] = ffma2(a2, b2, acc[2][2]);
            acc[3][0] = ffma2(a3, b0, acc[3][0]);
            acc[3][1] = ffma2(a3, b1, acc[3][1]);
            acc[3][2] = ffma2(a3, b2, acc[3][2]);
        }

#pragma unroll
        for (int i = 0; i < 4; i++) {
            float* gp = g_part + ((size_t)(kidx * BSZ + ty * 4 + i)) * N3
                        + bn * 96 + tx * 6;
#pragma unroll
            for (int j = 0; j < 3; j++) {
                float2 v = unpack2(acc[i][j]);
                *(float2*)&gp[2 * j] = v;
            }
        }
        grid_barrier(&s_epoch, false);

        // ---- phase B: reduce partials + gates ----
        {
            int e = cta * 512 + tid * 2;
            int b = e >> 10, d = e & 1023;
            float2 pr = {0.f, 0.f}, pz = {0.f, 0.f}, pn = {0.f, 0.f};
#pragma unroll
            for (int k = 0; k < 4; k++) {
                const float* g = g_part + (size_t)(k * BSZ + b) * N3;
                float2 v;
                v = __ldcg((const float2*)&g[d]);            pr.x += v.x; pr.y += v.y;
                v = __ldcg((const float2*)&g[DIM + d]);      pz.x += v.x; pz.y += v.y;
                v = __ldcg((const float2*)&g[2 * DIM + d]);  pn.x += v.x; pn.y += v.y;
            }
            const float* xp = g_xproj + (size_t)(t * BSZ + b) * N3;
            float2 xr = *(const float2*)&xp[d];
            float2 xz = *(const float2*)&xp[DIM + d];
            float2 xn = *(const float2*)&xp[2 * DIM + d];
            float2 h2 = __ldcg((const float2*)&g_heff[b * DIM + d]);
            float2 bh = *(const float2*)&b_hn[d];

            float rx = 1.f / (1.f + __expf(-(xr.x + pr.x)));
            float ry = 1.f / (1.f + __expf(-(xr.y + pr.y)));
            float zx = 1.f / (1.f + __expf(-(xz.x + pz.x)));
            float zy = 1.f / (1.f + __expf(-(xz.y + pz.y)));
            float nx = tanhf(xn.x + rx * (pn.x + bh.x));
            float ny = tanhf(xn.y + ry * (pn.y + bh.y));
            float2 hnew;
            hnew.x = (1.f - zx) * nx + zx * h2.x;
            hnew.y = (1.f - zy) * ny + zy * h2.y;

            *(float2*)&ys[((size_t)t * BSZ + b) * DIM + d] = hnew;
            if (t == T_STEPS - 1) {
                *(float2*)&out[b * DIM + d] = hnew;
            } else {
                bool dn = read_done(dones, (t + 1) * BSZ + b, is_byte);
                float2 he = hnew;
                if (dn)
                    he = *(const float2*)&hiddens[((size_t)(t + 1) * BSZ + b) * DIM + d];
                *(float2*)&g_heff[b * DIM + d] = he;
            }
        }
        grid_barrier(&s_epoch, t == T_STEPS - 1);
    }
}

// ---------------------------------------------------------------------------
extern "C" void kernel_launch(void* const* d_in, const int* in_sizes, int n_in,
                              void* d_out, int out_size) {
    const float* ins        = (const float*)d_in[0];
    const float* hiddens    = (const float*)d_in[1];
    const void*  dones      = d_in[2];
    const float* init_carry = (const float*)d_in[3];
    const float* W_i        = (const float*)d_in[4];
    const float* W_h        = (const float*)d_in[5];
    const float* b_i        = (const float*)d_in[6];
    const float* b_hn       = (const float*)d_in[7];
    float* out = (float*)d_out;

    cudaFuncSetAttribute(scan_kernel,
                         cudaFuncAttributeMaxDynamicSharedMemorySize, SCAN_SMEM);

    detect_dones_kernel<<<1, 1>>>((const unsigned char*)dones);

    dim3 grid1(N3 / BN1, M_TOTAL / BM1);    // (48, 128)
    gemm_xproj_kernel<<<grid1, 256>>>(ins, W_i, b_i);

    scan_kernel<<<NCTA, NTHR, SCAN_SMEM>>>(hiddens, dones, init_carry,
                                           W_h, b_hn, out);
}

// round 7
// speedup vs baseline: 1.4229x; 1.4229x over previous
#include <cuda_runtime.h>
#include <cuda_bf16.h>
#include <math.h>
#include <cstdint>

// Problem constants
#define T_STEPS 256
#define BSZ     64
#define DIM     1024
#define N3      (3 * DIM)          // 3072
#define M_TOTAL (T_STEPS * BSZ)    // 16384
#define NCTA    128
#define NTHR    256

typedef unsigned long long ull;

// Scratch (__device__ globals; allocation-free rule)
__device__ float g_xproj[(size_t)M_TOTAL * N3];             // [T,B,3D] ~192 MiB
__device__ float g_part[4 * BSZ * N3];                      // split-K partials
__device__ float g_heff[BSZ * DIM];                         // reset-applied h
__device__ __nv_bfloat16 g_ins_hi[(size_t)M_TOTAL * DIM];   // 32 MiB
__device__ __nv_bfloat16 g_ins_lo[(size_t)M_TOTAL * DIM];   // 32 MiB
__device__ __nv_bfloat16 g_wi_hi[(size_t)N3 * DIM];         // [N,K] transposed
__device__ __nv_bfloat16 g_wi_lo[(size_t)N3 * DIM];
__device__ int   g_dones_is_byte;
__device__ unsigned g_bar_count;
__device__ unsigned g_bar_epoch;

// ---------------- packed f32x2 helpers ----------------
__device__ __forceinline__ ull ffma2(ull a, ull b, ull c) {
    ull d;
    asm("fma.rn.f32x2 %0, %1, %2, %3;" : "=l"(d) : "l"(a), "l"(b), "l"(c));
    return d;
}
__device__ __forceinline__ ull pack2(float x, float y) {
    ull d;
    asm("mov.b64 %0, {%1, %2};" : "=l"(d) : "f"(x), "f"(y));
    return d;
}
__device__ __forceinline__ float2 unpack2(ull v) {
    float2 r;
    asm("mov.b64 {%0, %1}, %2;" : "=f"(r.x), "=f"(r.y) : "l"(v));
    return r;
}

__device__ __forceinline__ uint32_t smem_u32(const void* p) {
    uint32_t a;
    asm("{ .reg .u64 t; cvta.to.shared.u64 t, %1; cvt.u32.u64 %0, t; }"
        : "=r"(a) : "l"(p));
    return a;
}

// ---------------- dones dtype probe ----------------
__global__ void detect_dones_kernel(const unsigned char* __restrict__ p) {
    int nz = 0;
    for (int i = 0; i < 256; i++)
        if ((i & 3) != 0 && p[i] != 0) nz++;
    g_dones_is_byte = (nz > 0) ? 1 : 0;
}
__device__ __forceinline__ bool read_done(const void* dones, int idx, int is_byte) {
    if (is_byte) return ((const unsigned char*)dones)[idx] != 0;
    return ((const int*)dones)[idx] != 0;
}

// ---------------- bf16 split conversions ----------------
__global__ __launch_bounds__(256) void convert_ins_kernel(const float* __restrict__ A) {
    size_t i = ((size_t)blockIdx.x * 256 + threadIdx.x) * 4;
    float4 v = *(const float4*)(A + i);
    __nv_bfloat16 h0 = __float2bfloat16_rn(v.x);
    __nv_bfloat16 h1 = __float2bfloat16_rn(v.y);
    __nv_bfloat16 h2 = __float2bfloat16_rn(v.z);
    __nv_bfloat16 h3 = __float2bfloat16_rn(v.w);
    __nv_bfloat16 l0 = __float2bfloat16_rn(v.x - __bfloat162float(h0));
    __nv_bfloat16 l1 = __float2bfloat16_rn(v.y - __bfloat162float(h1));
    __nv_bfloat16 l2 = __float2bfloat16_rn(v.z - __bfloat162float(h2));
    __nv_bfloat16 l3 = __float2bfloat16_rn(v.w - __bfloat162float(h3));
    __nv_bfloat162* hp = (__nv_bfloat162*)(g_ins_hi + i);
    __nv_bfloat162* lp = (__nv_bfloat162*)(g_ins_lo + i);
    hp[0] = __nv_bfloat162(h0, h1); hp[1] = __nv_bfloat162(h2, h3);
    lp[0] = __nv_bfloat162(l0, l1); lp[1] = __nv_bfloat162(l2, l3);
}

// W_i [K,N] f32 -> [N,K] bf16 hi/lo, 32x32 SMEM tile transpose (coalesced both sides)
__global__ __launch_bounds__(256) void convert_w_kernel(const float* __restrict__ W) {
    __shared__ float tile[32][33];
    const int nb = blockIdx.x * 32;      // N3 / 32 = 96
    const int kb = blockIdx.y * 32;      // DIM / 32 = 32
    const int c = threadIdx.x & 31;
    const int r8 = threadIdx.x >> 5;     // 0..7
#pragma unroll
    for (int s = 0; s < 4; s++) {
        int r = r8 + s * 8;
        tile[r][c] = W[(size_t)(kb + r) * N3 + nb + c];
    }
    __syncthreads();
#pragma unroll
    for (int s = 0; s < 4; s++) {
        int r = r8 + s * 8;              // output n-row index within tile
        float v = tile[c][r];            // W[kb+c][nb+r]
        __nv_bfloat16 h = __float2bfloat16_rn(v);
        __nv_bfloat16 l = __float2bfloat16_rn(v - __bfloat162float(h));
        size_t o = (size_t)(nb + r) * DIM + kb + c;
        g_wi_hi[o] = h;
        g_wi_lo[o] = l;
    }
}

// ---------------------------------------------------------------------------
// Tensor-core xproj via mma.sync (HMMA, no 'a'-feature needed):
//   g_xproj = ins @ W_i + b_i, bf16x3 (Ahi*Bhi + Ahi*Blo + Alo*Bhi)
// BM=128, BN=128, BK=32. 8 warps (2m x 4n), warp tile 64x32.
// SMEM row stride 40 bf16 (80 B): ldmatrix conflict-free (m*20 mod 32 distinct).
// ---------------------------------------------------------------------------
#define XSTRIDE 40   // bf16 elements per SMEM row

__device__ __forceinline__ void ldsm_x4(uint32_t addr, uint32_t* r) {
    asm volatile("ldmatrix.sync.aligned.m8n8.x4.shared.b16 {%0,%1,%2,%3}, [%4];"
                 : "=r"(r[0]), "=r"(r[1]), "=r"(r[2]), "=r"(r[3]) : "r"(addr));
}
__device__ __forceinline__ void mma16816(float* c, const uint32_t* a,
                                         uint32_t b0, uint32_t b1) {
    asm volatile(
        "mma.sync.aligned.m16n8k16.row.col.f32.bf16.bf16.f32 "
        "{%0,%1,%2,%3}, {%4,%5,%6,%7}, {%8,%9}, {%0,%1,%2,%3};"
        : "+f"(c[0]), "+f"(c[1]), "+f"(c[2]), "+f"(c[3])
        : "r"(a[0]), "r"(a[1]), "r"(a[2]), "r"(a[3]), "r"(b0), "r"(b1));
}

__global__ __launch_bounds__(256, 1) void gemm_xproj_mma_kernel(
    const float* __restrict__ bias)
{
    __shared__ __align__(16) __nv_bfloat16 As[2][128 * XSTRIDE];
    __shared__ __align__(16) __nv_bfloat16 Bs[2][128 * XSTRIDE];

    const int tid = threadIdx.x;
    const int wid = tid >> 5;
    const int lane = tid & 31;
    const int wm = wid >> 2;            // 0..1 (64 m each)
    const int wn = wid & 3;             // 0..3 (32 n each)
    const int bn = blockIdx.x;          // 0..23
    const int bm = blockIdx.y;          // 0..127

    const __nv_bfloat16* Ahi = g_ins_hi + (size_t)bm * 128 * DIM;
    const __nv_bfloat16* Alo = g_ins_lo + (size_t)bm * 128 * DIM;
    const __nv_bfloat16* Bhi = g_wi_hi + (size_t)bn * 128 * DIM;
    const __nv_bfloat16* Blo = g_wi_lo + (size_t)bn * 128 * DIM;

    // global load coords: 512 16B-chunks per tile, 2 per thread
    const int c0 = tid, c1 = tid + 256;
    const int m0 = c0 >> 2, kc0 = c0 & 3;
    const int m1 = c1 >> 2, kc1 = c1 & 3;

    // ldmatrix per-thread base offsets (bf16 elements within buffer)
    const int a_off = (wm * 64 + (lane & 15)) * XSTRIDE + (lane >> 4) * 8;
    const int b_off = (wn * 32 + (lane & 7) + ((lane >> 4) & 1) * 8) * XSTRIDE
                      + ((lane >> 3) & 1) * 8;

    float acc[4][4][4];
#pragma unroll
    for (int i = 0; i < 4; i++)
#pragma unroll
        for (int j = 0; j < 4; j++)
#pragma unroll
            for (int q = 0; q < 4; q++) acc[i][j][q] = 0.f;

    uint4 pa0, pa1, pb0, pb1;

    // prologue: tile 0 (pass 0, k0 = 0)
    pa0 = *(const uint4*)(Ahi + (size_t)m0 * DIM + kc0 * 8);
    pa1 = *(const uint4*)(Ahi + (size_t)m1 * DIM + kc1 * 8);
    pb0 = *(const uint4*)(Bhi + (size_t)m0 * DIM + kc0 * 8);
    pb1 = *(const uint4*)(Bhi + (size_t)m1 * DIM + kc1 * 8);
    *(uint4*)&As[0][m0 * XSTRIDE + kc0 * 8] = pa0;
    *(uint4*)&As[0][m1 * XSTRIDE + kc1 * 8] = pa1;
    *(uint4*)&Bs[0][m0 * XSTRIDE + kc0 * 8] = pb0;
    *(uint4*)&Bs[0][m1 * XSTRIDE + kc1 * 8] = pb1;
    __syncthreads();

    int cur = 0;
    for (int kt = 0; kt < 96; kt++) {
        // prefetch next tile into regs
        if (kt + 1 < 96) {
            int nt = kt + 1;
            int pass = nt >> 5;
            int k0 = (nt & 31) * 32;
            const __nv_bfloat16* Ap = (pass < 2) ? Ahi : Alo;
            const __nv_bfloat16* Bp = (pass == 1) ? Blo : Bhi;
            pa0 = *(const uint4*)(Ap + (size_t)m0 * DIM + k0 + kc0 * 8);
            pa1 = *(const uint4*)(Ap + (size_t)m1 * DIM + k0 + kc1 * 8);
            pb0 = *(const uint4*)(Bp + (size_t)m0 * DIM + k0 + kc0 * 8);
            pb1 = *(const uint4*)(Bp + (size_t)m1 * DIM + k0 + kc1 * 8);
        }

        // compute on current buffer: 2 k-steps of 16
        const uint32_t a_base = smem_u32(&As[cur][0]) + a_off * 2;
        const uint32_t b_base = smem_u32(&Bs[cur][0]) + b_off * 2;
#pragma unroll
        for (int ks = 0; ks < 2; ks++) {
            uint32_t af[4][4], bf[2][4];
#pragma unroll
            for (int i = 0; i < 4; i++)
                ldsm_x4(a_base + (i * 16 * XSTRIDE + ks * 16) * 2, af[i]);
#pragma unroll
            for (int jj = 0; jj < 2; jj++)
                ldsm_x4(b_base + (jj * 16 * XSTRIDE + ks * 16) * 2, bf[jj]);
#pragma unroll
            for (int i = 0; i < 4; i++) {
#pragma unroll
                for (int j = 0; j < 4; j++) {
                    mma16816(acc[i][j], af[i],
                             bf[j >> 1][(j & 1) * 2], bf[j >> 1][(j & 1) * 2 + 1]);
                }
            }
        }

        // store prefetched tile into the other buffer
        if (kt + 1 < 96) {
            int nxt = cur ^ 1;
            *(uint4*)&As[nxt][m0 * XSTRIDE + kc0 * 8] = pa0;
            *(uint4*)&As[nxt][m1 * XSTRIDE + kc1 * 8] = pa1;
            *(uint4*)&Bs[nxt][m0 * XSTRIDE + kc0 * 8] = pb0;
            *(uint4*)&Bs[nxt][m1 * XSTRIDE + kc1 * 8] = pb1;
        }
        __syncthreads();
        cur ^= 1;
    }

    // epilogue: acc layout -> (m = group, n = tig*2), rows +0/+8
    const int groupID = lane >> 2, tig = lane & 3;
#pragma unroll
    for (int i = 0; i < 4; i++) {
        int mrow = bm * 128 + wm * 64 + i * 16 + groupID;
        float* row0 = g_xproj + (size_t)mrow * N3;
        float* row1 = g_xproj + (size_t)(mrow + 8) * N3;
#pragma unroll
        for (int j = 0; j < 4; j++) {
            int ncol = bn * 128 + wn * 32 + j * 8 + tig * 2;
            float2 bv = *(const float2*)&bias[ncol];
            float2 o0, o1;
            o0.x = acc[i][j][0] + bv.x; o0.y = acc[i][j][1] + bv.y;
            o1.x = acc[i][j][2] + bv.x; o1.y = acc[i][j][3] + bv.y;
            *(float2*)&row0[ncol] = o0;
            *(float2*)&row1[ncol] = o1;
        }
    }
}

// ---------------------------------------------------------------------------
// Persistent scan kernel — proven R2 version (unchanged).
// ---------------------------------------------------------------------------
__device__ __forceinline__ void grid_barrier(unsigned* s_epoch, bool last) {
    __threadfence();
    __syncthreads();
    if (threadIdx.x == 0) {
        unsigned my = *s_epoch;
        unsigned prev = atomicAdd(&g_bar_count, 1u);
        if (prev == NCTA - 1) {
            g_bar_count = 0;
            __threadfence();
            atomicExch(&g_bar_epoch, last ? 0u : (my + 1u));
        } else {
            volatile unsigned* ep = &g_bar_epoch;
            while (*ep == my) { __nanosleep(64); }
            __threadfence();
        }
        *s_epoch = my + 1u;
    }
    __syncthreads();
}

#define SCAN_SMEM ((256 * 96 + BSZ * 256) * 4)   // 163840 B -> 1 CTA/SM

__global__ __launch_bounds__(NTHR, 1) void scan_kernel(
    const float* __restrict__ hiddens,
    const void*  __restrict__ dones,
    const float* __restrict__ init_carry,
    const float* __restrict__ W_h,
    const float* __restrict__ b_hn,
    float* __restrict__ out)
{
    extern __shared__ float smemf[];
    float* Bs = smemf;                    // [256][96]
    float* Hs = smemf + 256 * 96;         // [64][256]
    __shared__ unsigned s_epoch;

    const int tid = threadIdx.x;
    const int cta = blockIdx.x;
    const int bn = cta & 31;
    const int kidx = cta >> 5;
    const int kbase = kidx * 256;
    const int tx = tid & 15;
    const int ty = tid >> 4;
    const int is_byte = g_dones_is_byte;
    float* ys = out + (size_t)BSZ * DIM;

    if (tid == 0) s_epoch = 0;

    for (int i = tid; i < 256 * 24; i += NTHR) {
        int k = i / 24, c4 = (i % 24) * 4;
        *(float4*)&Bs[k * 96 + c4] =
            *(const float4*)&W_h[(size_t)(kbase + k) * N3 + bn * 96 + c4];
    }

    {
        int e = cta * 512 + tid * 2;
        int b = e >> 10, d = e & 1023;
        bool dn = read_done(dones, b, is_byte);
        const float* src = dn ? (hiddens + (size_t)b * DIM)
                              : (init_carry + (size_t)b * DIM);
        float2 v = *(const float2*)&src[d];
        *(float2*)&g_heff[b * DIM + d] = v;
    }
    grid_barrier(&s_epoch, false);

    for (int t = 0; t < T_STEPS; t++) {
        for (int i = tid; i < BSZ * 64; i += NTHR) {
            int b = i >> 6;
            int c4 = (i & 63) * 4;
            float4 v = __ldcg((const float4*)&g_heff[b * DIM + kbase + c4]);
            *(float4*)&Hs[b * 256 + c4] = v;
        }
        __syncthreads();

        ull acc[4][3];
#pragma unroll
        for (int i = 0; i < 4; i++)
#pragma unroll
            for (int j = 0; j < 3; j++) acc[i][j] = 0ull;

        const float* hrow0 = Hs + (ty * 4 + 0) * 256;
        const float* hrow1 = Hs + (ty * 4 + 1) * 256;
        const float* hrow2 = Hs + (ty * 4 + 2) * 256;
        const float* hrow3 = Hs + (ty * 4 + 3) * 256;
        const float* bcol = Bs + tx * 6;

#pragma unroll 8
        for (int k = 0; k < 256; k++) {
            ull b0 = *(const ull*)&bcol[k * 96 + 0];
            ull b1 = *(const ull*)&bcol[k * 96 + 2];
            ull b2 = *(const ull*)&bcol[k * 96 + 4];
            ull a0 = pack2(hrow0[k], hrow0[k]);
            ull a1 = pack2(hrow1[k], hrow1[k]);
            ull a2 = pack2(hrow2[k], hrow2[k]);
            ull a3 = pack2(hrow3[k], hrow3[k]);
            acc[0][0] = ffma2(a0, b0, acc[0][0]);
            acc[0][1] = ffma2(a0, b1, acc[0][1]);
            acc[0][2] = ffma2(a0, b2, acc[0][2]);
            acc[1][0] = ffma2(a1, b0, acc[1][0]);
            acc[1][1] = ffma2(a1, b1, acc[1][1]);
            acc[1][2] = ffma2(a1, b2, acc[1][2]);
            acc[2][0] = ffma2(a2, b0, acc[2][0]);
            acc[2][1] = ffma2(a2, b1, acc[2][1]);
            acc[2][2] = ffma2(a2, b2, acc[2][2]);
            acc[3][0] = ffma2(a3, b0, acc[3][0]);
            acc[3][1] = ffma2(a3, b1, acc[3][1]);
            acc[3][2] = ffma2(a3, b2, acc[3][2]);
        }

#pragma unroll
        for (int i = 0; i < 4; i++) {
            float* gp = g_part + ((size_t)(kidx * BSZ + ty * 4 + i)) * N3
                        + bn * 96 + tx * 6;
#pragma unroll
            for (int j = 0; j < 3; j++) {
                float2 v = unpack2(acc[i][j]);
                *(float2*)&gp[2 * j] = v;
            }
        }
        grid_barrier(&s_epoch, false);

        {
            int e = cta * 512 + tid * 2;
            int b = e >> 10, d = e & 1023;
            float2 pr = {0.f, 0.f}, pz = {0.f, 0.f}, pn = {0.f, 0.f};
#pragma unroll
            for (int k = 0; k < 4; k++) {
                const float* g = g_part + (size_t)(k * BSZ + b) * N3;
                float2 v;
                v = __ldcg((const float2*)&g[d]);            pr.x += v.x; pr.y += v.y;
                v = __ldcg((const float2*)&g[DIM + d]);      pz.x += v.x; pz.y += v.y;
                v = __ldcg((const float2*)&g[2 * DIM + d]);  pn.x += v.x; pn.y += v.y;
            }
            const float* xp = g_xproj + (size_t)(t * BSZ + b) * N3;
            float2 xr = *(const float2*)&xp[d];
            float2 xz = *(const float2*)&xp[DIM + d];
            float2 xn = *(const float2*)&xp[2 * DIM + d];
            float2 h2 = __ldcg((const float2*)&g_heff[b * DIM + d]);
            float2 bh = *(const float2*)&b_hn[d];

            float rx = 1.f / (1.f + __expf(-(xr.x + pr.x)));
            float ry = 1.f / (1.f + __expf(-(xr.y + pr.y)));
            float zx = 1.f / (1.f + __expf(-(xz.x + pz.x)));
            float zy = 1.f / (1.f + __expf(-(xz.y + pz.y)));
            float nx = tanhf(xn.x + rx * (pn.x + bh.x));
            float ny = tanhf(xn.y + ry * (pn.y + bh.y));
            float2 hnew;
            hnew.x = (1.f - zx) * nx + zx * h2.x;
            hnew.y = (1.f - zy) * ny + zy * h2.y;

            *(float2*)&ys[((size_t)t * BSZ + b) * DIM + d] = hnew;
            if (t == T_STEPS - 1) {
                *(float2*)&out[b * DIM + d] = hnew;
            } else {
                bool dn = read_done(dones, (t + 1) * BSZ + b, is_byte);
                float2 he = hnew;
                if (dn)
                    he = *(const float2*)&hiddens[((size_t)(t + 1) * BSZ + b) * DIM + d];
                *(float2*)&g_heff[b * DIM + d] = he;
            }
        }
        grid_barrier(&s_epoch, t == T_STEPS - 1);
    }
}

// ---------------------------------------------------------------------------
extern "C" void kernel_launch(void* const* d_in, const int* in_sizes, int n_in,
                              void* d_out, int out_size) {
    const float* ins        = (const float*)d_in[0];
    const float* hiddens    = (const float*)d_in[1];
    const void*  dones      = d_in[2];
    const float* init_carry = (const float*)d_in[3];
    const float* W_i        = (const float*)d_in[4];
    const float* W_h        = (const float*)d_in[5];
    const float* b_i        = (const float*)d_in[6];
    const float* b_hn       = (const float*)d_in[7];
    float* out = (float*)d_out;

    cudaFuncSetAttribute(scan_kernel,
                         cudaFuncAttributeMaxDynamicSharedMemorySize, SCAN_SMEM);

    detect_dones_kernel<<<1, 1>>>((const unsigned char*)dones);

    // bf16 hi/lo splits
    convert_ins_kernel<<<(int)(((size_t)M_TOTAL * DIM / 4) / 256), 256>>>(ins);
    {
        dim3 gw(N3 / 32, DIM / 32);       // (96, 32)
        convert_w_kernel<<<gw, 256>>>(W_i);
    }

    // HMMA xproj
    {
        dim3 grid(N3 / 128, M_TOTAL / 128);   // (24, 128)
        gemm_xproj_mma_kernel<<<grid, 256>>>(b_i);
    }

    scan_kernel<<<NCTA, NTHR, SCAN_SMEM>>>(hiddens, dones, init_carry,
                                           W_h, b_hn, out);
}

// round 8
// speedup vs baseline: 2.0334x; 1.4291x over previous
#include <cuda_runtime.h>
#include <cuda_bf16.h>
#include <math.h>
#include <cstdint>

// Problem constants
#define T_STEPS 256
#define BSZ     64
#define DIM     1024
#define N3      (3 * DIM)          // 3072
#define M_TOTAL (T_STEPS * BSZ)    // 16384
#define NCTA    128
#define NTHR    256

typedef unsigned long long ull;

// Scratch (__device__ globals; allocation-free rule)
__device__ float g_xproj[(size_t)M_TOTAL * N3];             // [T,B,3D] ~192 MiB
__device__ float g_part[4 * BSZ * N3];                      // split-K partials
__device__ float g_heff[BSZ * DIM];                         // reset-applied h (f32)
__device__ __nv_bfloat16 g_hh[BSZ * DIM];                   // h hi split
__device__ __nv_bfloat16 g_hl[BSZ * DIM];                   // h lo split
__device__ __nv_bfloat16 g_ins_hi[(size_t)M_TOTAL * DIM];   // 32 MiB
__device__ __nv_bfloat16 g_ins_lo[(size_t)M_TOTAL * DIM];   // 32 MiB
__device__ __nv_bfloat16 g_wi_hi[(size_t)N3 * DIM];         // W_i [N,K]
__device__ __nv_bfloat16 g_wi_lo[(size_t)N3 * DIM];
__device__ __nv_bfloat16 g_wh_hi[(size_t)N3 * DIM];         // W_h [N,K]
__device__ __nv_bfloat16 g_wh_lo[(size_t)N3 * DIM];
__device__ int   g_dones_is_byte;
__device__ unsigned g_bar_count;
__device__ unsigned g_bar_epoch;

__device__ __forceinline__ uint32_t smem_u32(const void* p) {
    uint32_t a;
    asm("{ .reg .u64 t; cvta.to.shared.u64 t, %1; cvt.u32.u64 %0, t; }"
        : "=r"(a) : "l"(p));
    return a;
}

// ---------------- dones dtype probe ----------------
__global__ void detect_dones_kernel(const unsigned char* __restrict__ p) {
    int nz = 0;
    for (int i = 0; i < 256; i++)
        if ((i & 3) != 0 && p[i] != 0) nz++;
    g_dones_is_byte = (nz > 0) ? 1 : 0;
}
__device__ __forceinline__ bool read_done(const void* dones, int idx, int is_byte) {
    if (is_byte) return ((const unsigned char*)dones)[idx] != 0;
    return ((const int*)dones)[idx] != 0;
}

// ---------------- bf16 split conversions ----------------
__global__ __launch_bounds__(256) void convert_ins_kernel(const float* __restrict__ A) {
    size_t i = ((size_t)blockIdx.x * 256 + threadIdx.x) * 4;
    float4 v = *(const float4*)(A + i);
    __nv_bfloat16 h0 = __float2bfloat16_rn(v.x);
    __nv_bfloat16 h1 = __float2bfloat16_rn(v.y);
    __nv_bfloat16 h2 = __float2bfloat16_rn(v.z);
    __nv_bfloat16 h3 = __float2bfloat16_rn(v.w);
    __nv_bfloat16 l0 = __float2bfloat16_rn(v.x - __bfloat162float(h0));
    __nv_bfloat16 l1 = __float2bfloat16_rn(v.y - __bfloat162float(h1));
    __nv_bfloat16 l2 = __float2bfloat16_rn(v.z - __bfloat162float(h2));
    __nv_bfloat16 l3 = __float2bfloat16_rn(v.w - __bfloat162float(h3));
    __nv_bfloat162* hp = (__nv_bfloat162*)(g_ins_hi + i);
    __nv_bfloat162* lp = (__nv_bfloat162*)(g_ins_lo + i);
    hp[0] = __nv_bfloat162(h0, h1); hp[1] = __nv_bfloat162(h2, h3);
    lp[0] = __nv_bfloat162(l0, l1); lp[1] = __nv_bfloat162(l2, l3);
}

// [K,N3] f32 -> [N3,K] bf16 hi/lo, 32x32 SMEM tile transpose
__global__ __launch_bounds__(256) void convert_w_kernel(
    const float* __restrict__ W, __nv_bfloat16* __restrict__ hi,
    __nv_bfloat16* __restrict__ lo)
{
    __shared__ float tile[32][33];
    const int nb = blockIdx.x * 32;
    const int kb = blockIdx.y * 32;
    const int c = threadIdx.x & 31;
    const int r8 = threadIdx.x >> 5;
#pragma unroll
    for (int s = 0; s < 4; s++) {
        int r = r8 + s * 8;
        tile[r][c] = W[(size_t)(kb + r) * N3 + nb + c];
    }
    __syncthreads();
#pragma unroll
    for (int s = 0; s < 4; s++) {
        int r = r8 + s * 8;
        float v = tile[c][r];
        __nv_bfloat16 h = __float2bfloat16_rn(v);
        __nv_bfloat16 l = __float2bfloat16_rn(v - __bfloat162float(h));
        size_t o = (size_t)(nb + r) * DIM + kb + c;
        hi[o] = h;
        lo[o] = l;
    }
}

// ---------------- HMMA primitives ----------------
__device__ __forceinline__ void ldsm_x4(uint32_t addr, uint32_t* r) {
    asm volatile("ldmatrix.sync.aligned.m8n8.x4.shared.b16 {%0,%1,%2,%3}, [%4];"
                 : "=r"(r[0]), "=r"(r[1]), "=r"(r[2]), "=r"(r[3]) : "r"(addr));
}
__device__ __forceinline__ void mma16816(float* c, const uint32_t* a,
                                         uint32_t b0, uint32_t b1) {
    asm volatile(
        "mma.sync.aligned.m16n8k16.row.col.f32.bf16.bf16.f32 "
        "{%0,%1,%2,%3}, {%4,%5,%6,%7}, {%8,%9}, {%0,%1,%2,%3};"
        : "+f"(c[0]), "+f"(c[1]), "+f"(c[2]), "+f"(c[3])
        : "r"(a[0]), "r"(a[1]), "r"(a[2]), "r"(a[3]), "r"(b0), "r"(b1));
}

// ---------------------------------------------------------------------------
// HMMA xproj (unchanged from R7, proven): g_xproj = ins @ W_i + b_i, bf16x3.
// ---------------------------------------------------------------------------
#define XSTRIDE 40

__global__ __launch_bounds__(256, 1) void gemm_xproj_mma_kernel(
    const float* __restrict__ bias)
{
    __shared__ __align__(16) __nv_bfloat16 As[2][128 * XSTRIDE];
    __shared__ __align__(16) __nv_bfloat16 Bs[2][128 * XSTRIDE];

    const int tid = threadIdx.x;
    const int wid = tid >> 5;
    const int lane = tid & 31;
    const int wm = wid >> 2;
    const int wn = wid & 3;
    const int bn = blockIdx.x;
    const int bm = blockIdx.y;

    const __nv_bfloat16* Ahi = g_ins_hi + (size_t)bm * 128 * DIM;
    const __nv_bfloat16* Alo = g_ins_lo + (size_t)bm * 128 * DIM;
    const __nv_bfloat16* Bhi = g_wi_hi + (size_t)bn * 128 * DIM;
    const __nv_bfloat16* Blo = g_wi_lo + (size_t)bn * 128 * DIM;

    const int c0 = tid, c1 = tid + 256;
    const int m0 = c0 >> 2, kc0 = c0 & 3;
    const int m1 = c1 >> 2, kc1 = c1 & 3;

    const int a_off = (wm * 64 + (lane & 15)) * XSTRIDE + (lane >> 4) * 8;
    const int b_off = (wn * 32 + (lane & 7) + ((lane >> 4) & 1) * 8) * XSTRIDE
                      + ((lane >> 3) & 1) * 8;

    float acc[4][4][4];
#pragma unroll
    for (int i = 0; i < 4; i++)
#pragma unroll
        for (int j = 0; j < 4; j++)
#pragma unroll
            for (int q = 0; q < 4; q++) acc[i][j][q] = 0.f;

    uint4 pa0, pa1, pb0, pb1;
    pa0 = *(const uint4*)(Ahi + (size_t)m0 * DIM + kc0 * 8);
    pa1 = *(const uint4*)(Ahi + (size_t)m1 * DIM + kc1 * 8);
    pb0 = *(const uint4*)(Bhi + (size_t)m0 * DIM + kc0 * 8);
    pb1 = *(const uint4*)(Bhi + (size_t)m1 * DIM + kc1 * 8);
    *(uint4*)&As[0][m0 * XSTRIDE + kc0 * 8] = pa0;
    *(uint4*)&As[0][m1 * XSTRIDE + kc1 * 8] = pa1;
    *(uint4*)&Bs[0][m0 * XSTRIDE + kc0 * 8] = pb0;
    *(uint4*)&Bs[0][m1 * XSTRIDE + kc1 * 8] = pb1;
    __syncthreads();

    int cur = 0;
    for (int kt = 0; kt < 96; kt++) {
        if (kt + 1 < 96) {
            int nt = kt + 1;
            int pass = nt >> 5;
            int k0 = (nt & 31) * 32;
            const __nv_bfloat16* Ap = (pass < 2) ? Ahi : Alo;
            const __nv_bfloat16* Bp = (pass == 1) ? Blo : Bhi;
            pa0 = *(const uint4*)(Ap + (size_t)m0 * DIM + k0 + kc0 * 8);
            pa1 = *(const uint4*)(Ap + (size_t)m1 * DIM + k0 + kc1 * 8);
            pb0 = *(const uint4*)(Bp + (size_t)m0 * DIM + k0 + kc0 * 8);
            pb1 = *(const uint4*)(Bp + (size_t)m1 * DIM + k0 + kc1 * 8);
        }

        const uint32_t a_base = smem_u32(&As[cur][0]) + a_off * 2;
        const uint32_t b_base = smem_u32(&Bs[cur][0]) + b_off * 2;
#pragma unroll
        for (int ks = 0; ks < 2; ks++) {
            uint32_t af[4][4], bf[2][4];
#pragma unroll
            for (int i = 0; i < 4; i++)
                ldsm_x4(a_base + (i * 16 * XSTRIDE + ks * 16) * 2, af[i]);
#pragma unroll
            for (int jj = 0; jj < 2; jj++)
                ldsm_x4(b_base + (jj * 16 * XSTRIDE + ks * 16) * 2, bf[jj]);
#pragma unroll
            for (int i = 0; i < 4; i++)
#pragma unroll
                for (int j = 0; j < 4; j++)
                    mma16816(acc[i][j], af[i],
                             bf[j >> 1][(j & 1) * 2], bf[j >> 1][(j & 1) * 2 + 1]);
        }

        if (kt + 1 < 96) {
            int nxt = cur ^ 1;
            *(uint4*)&As[nxt][m0 * XSTRIDE + kc0 * 8] = pa0;
            *(uint4*)&As[nxt][m1 * XSTRIDE + kc1 * 8] = pa1;
            *(uint4*)&Bs[nxt][m0 * XSTRIDE + kc0 * 8] = pb0;
            *(uint4*)&Bs[nxt][m1 * XSTRIDE + kc1 * 8] = pb1;
        }
        __syncthreads();
        cur ^= 1;
    }

    const int groupID = lane >> 2, tig = lane & 3;
#pragma unroll
    for (int i = 0; i < 4; i++) {
        int mrow = bm * 128 + wm * 64 + i * 16 + groupID;
        float* row0 = g_xproj + (size_t)mrow * N3;
        float* row1 = g_xproj + (size_t)(mrow + 8) * N3;
#pragma unroll
        for (int j = 0; j < 4; j++) {
            int ncol = bn * 128 + wn * 32 + j * 8 + tig * 2;
            float2 bv = *(const float2*)&bias[ncol];
            float2 o0, o1;
            o0.x = acc[i][j][0] + bv.x; o0.y = acc[i][j][1] + bv.y;
            o1.x = acc[i][j][2] + bv.x; o1.y = acc[i][j][3] + bv.y;
            *(float2*)&row0[ncol] = o0;
            *(float2*)&row1[ncol] = o1;
        }
    }
}

// ---------------------------------------------------------------------------
// Lightweight grid barrier: syncthreads + leader release-atomic / acquire-poll.
// Cross-CTA data is read via __ldcg (L2), so no L1 flush needed.
// ---------------------------------------------------------------------------
__device__ __forceinline__ void grid_barrier(unsigned* s_epoch, bool last) {
    __syncthreads();
    if (threadIdx.x == 0) {
        unsigned my = *s_epoch;
        unsigned prev;
        asm volatile("atom.release.gpu.add.u32 %0, [%1], 1;"
                     : "=r"(prev) : "l"(&g_bar_count) : "memory");
        if (prev == NCTA - 1) {
            g_bar_count = 0;
            asm volatile("st.release.gpu.u32 [%0], %1;"
                         :: "l"(&g_bar_epoch), "r"(last ? 0u : (my + 1u))
                         : "memory");
        } else {
            unsigned e;
            do {
                __nanosleep(32);
                asm volatile("ld.acquire.gpu.u32 %0, [%1];"
                             : "=r"(e) : "l"(&g_bar_epoch) : "memory");
            } while (e == my);
        }
        *s_epoch = my + 1u;
    }
    __syncthreads();
}

// ---------------------------------------------------------------------------
// Persistent scan: phase A = HMMA bf16x3 partial GEMM (M=64, N=96, K=256/CTA),
// W_h slice hi/lo resident in SMEM; h staged hi/lo per step.
// Phase B = reduce partials + gates; emits h as f32 + bf16 hi/lo for t+1.
// ---------------------------------------------------------------------------
#define XS 264        // SMEM row stride in bf16 (528 B): bank walk 4r%32 distinct
#define SM_HHI 0
#define SM_HLO (64 * XS)
#define SM_WHI (128 * XS)
#define SM_WLO (224 * XS)
#define SCAN_SMEM (320 * XS * 2)   // 168960 B

__global__ __launch_bounds__(NTHR, 1) void scan_kernel(
    const float* __restrict__ hiddens,
    const void*  __restrict__ dones,
    const float* __restrict__ init_carry,
    const float* __restrict__ b_hn,
    float* __restrict__ out)
{
    extern __shared__ __nv_bfloat16 sm[];
    __shared__ unsigned s_epoch;

    const int tid = threadIdx.x;
    const int cta = blockIdx.x;
    const int bn = cta & 31;             // n-slice (96 gate cols)
    const int kidx = cta >> 5;           // k-chunk (256)
    const int kbase = kidx * 256;
    const int wid = tid >> 5;
    const int lane = tid & 31;
    const int wm = wid >> 1;             // 0..3 -> m16 tile
    const int wn = wid & 1;              // 0..1 -> n48 tile
    const int is_byte = g_dones_is_byte;
    float* ys = out + (size_t)BSZ * DIM;

    if (tid == 0) s_epoch = 0;

    // W_h slice -> SMEM once (hi+lo), [n][k] rows of 256 bf16
    for (int i = tid; i < 96 * 32; i += NTHR) {
        int row = i >> 5;
        int kc = (i & 31) * 8;
        size_t go = (size_t)(bn * 96 + row) * DIM + kbase + kc;
        *(uint4*)&sm[SM_WHI + row * XS + kc] = *(const uint4*)&g_wh_hi[go];
        *(uint4*)&sm[SM_WLO + row * XS + kc] = *(const uint4*)&g_wh_lo[go];
    }

    // initial h_eff (t=0 reset applied): f32 + bf16 splits
    {
        int e = cta * 512 + tid * 2;
        int b = e >> 10, d = e & 1023;
        bool dn = read_done(dones, b, is_byte);
        const float* src = dn ? (hiddens + (size_t)b * DIM)
                              : (init_carry + (size_t)b * DIM);
        float2 v = *(const float2*)&src[d];
        *(float2*)&g_heff[b * DIM + d] = v;
        __nv_bfloat16 h0 = __float2bfloat16_rn(v.x);
        __nv_bfloat16 h1 = __float2bfloat16_rn(v.y);
        __nv_bfloat16 l0 = __float2bfloat16_rn(v.x - __bfloat162float(h0));
        __nv_bfloat16 l1 = __float2bfloat16_rn(v.y - __bfloat162float(h1));
        *(__nv_bfloat162*)&g_hh[b * DIM + d] = __nv_bfloat162(h0, h1);
        *(__nv_bfloat162*)&g_hl[b * DIM + d] = __nv_bfloat162(l0, l1);
    }
    grid_barrier(&s_epoch, false);

    // ldmatrix lane offsets (bf16 elements)
    const int a_off = (wm * 16 + (lane & 15)) * XS + (lane >> 4) * 8;
    const int b_off = (wn * 48 + (lane & 7) + ((lane >> 4) & 1) * 8) * XS
                      + ((lane >> 3) & 1) * 8;
    const int groupID = lane >> 2, tig = lane & 3;

    for (int t = 0; t < T_STEPS; t++) {
        // ---- stage h chunk hi/lo ----
        for (int i = tid; i < 64 * 32; i += NTHR) {
            int row = i >> 5;
            int kc = (i & 31) * 8;
            size_t go = (size_t)row * DIM + kbase + kc;
            *(uint4*)&sm[SM_HHI + row * XS + kc] =
                __ldcg((const uint4*)&g_hh[go]);
            *(uint4*)&sm[SM_HLO + row * XS + kc] =
                __ldcg((const uint4*)&g_hl[go]);
        }
        __syncthreads();

        // ---- phase A: 3-pass HMMA, warp tile m16 x n48 ----
        float acc[6][4];
#pragma unroll
        for (int j = 0; j < 6; j++)
#pragma unroll
            for (int q = 0; q < 4; q++) acc[j][q] = 0.f;

#pragma unroll
        for (int pass = 0; pass < 3; pass++) {
            const uint32_t ab = smem_u32(sm) +
                ((pass == 1 ? SM_HLO : SM_HHI) + a_off) * 2;
            const uint32_t bb = smem_u32(sm) +
                ((pass == 2 ? SM_WLO : SM_WHI) + b_off) * 2;
#pragma unroll 4
            for (int ks = 0; ks < 16; ks++) {
                uint32_t af[4], bfr[3][4];
                ldsm_x4(ab + ks * 32, af);
#pragma unroll
                for (int jt = 0; jt < 3; jt++)
                    ldsm_x4(bb + jt * 16 * XS * 2 + ks * 32, bfr[jt]);
#pragma unroll
                for (int j = 0; j < 6; j++)
                    mma16816(acc[j], af,
                             bfr[j >> 1][(j & 1) * 2], bfr[j >> 1][(j & 1) * 2 + 1]);
            }
        }

        // epilogue: write f32 partials
        {
            int b0r = wm * 16 + groupID;       // batch rows b0r, b0r+8
            float* gp0 = g_part + ((size_t)(kidx * BSZ + b0r)) * N3 + bn * 96;
            float* gp1 = gp0 + (size_t)8 * N3;
#pragma unroll
            for (int j = 0; j < 6; j++) {
                int col = wn * 48 + j * 8 + tig * 2;
                float2 v0 = {acc[j][0], acc[j][1]};
                float2 v1 = {acc[j][2], acc[j][3]};
                *(float2*)&gp0[col] = v0;
                *(float2*)&gp1[col] = v1;
            }
        }
        grid_barrier(&s_epoch, false);

        // ---- phase B: reduce partials + gates ----
        {
            int e = cta * 512 + tid * 2;
            int b = e >> 10, d = e & 1023;
            float2 pr = {0.f, 0.f}, pz = {0.f, 0.f}, pn = {0.f, 0.f};
#pragma unroll
            for (int k = 0; k < 4; k++) {
                const float* g = g_part + (size_t)(k * BSZ + b) * N3;
                float2 v;
                v = __ldcg((const float2*)&g[d]);            pr.x += v.x; pr.y += v.y;
                v = __ldcg((const float2*)&g[DIM + d]);      pz.x += v.x; pz.y += v.y;
                v = __ldcg((const float2*)&g[2 * DIM + d]);  pn.x += v.x; pn.y += v.y;
            }
            const float* xp = g_xproj + (size_t)(t * BSZ + b) * N3;
            float2 xr = *(const float2*)&xp[d];
            float2 xz = *(const float2*)&xp[DIM + d];
            float2 xn = *(const float2*)&xp[2 * DIM + d];
            float2 h2 = __ldcg((const float2*)&g_heff[b * DIM + d]);
            float2 bh = *(const float2*)&b_hn[d];

            float rx = 1.f / (1.f + __expf(-(xr.x + pr.x)));
            float ry = 1.f / (1.f + __expf(-(xr.y + pr.y)));
            float zx = 1.f / (1.f + __expf(-(xz.x + pz.x)));
            float zy = 1.f / (1.f + __expf(-(xz.y + pz.y)));
            float nx = tanhf(xn.x + rx * (pn.x + bh.x));
            float ny = tanhf(xn.y + ry * (pn.y + bh.y));
            float2 hnew;
            hnew.x = (1.f - zx) * nx + zx * h2.x;
            hnew.y = (1.f - zy) * ny + zy * h2.y;

            *(float2*)&ys[((size_t)t * BSZ + b) * DIM + d] = hnew;
            if (t == T_STEPS - 1) {
                *(float2*)&out[b * DIM + d] = hnew;
            } else {
                bool dn = read_done(dones, (t + 1) * BSZ + b, is_byte);
                float2 he = hnew;
                if (dn)
                    he = *(const float2*)&hiddens[((size_t)(t + 1) * BSZ + b) * DIM + d];
                *(float2*)&g_heff[b * DIM + d] = he;
                __nv_bfloat16 h0 = __float2bfloat16_rn(he.x);
                __nv_bfloat16 h1 = __float2bfloat16_rn(he.y);
                __nv_bfloat16 l0 = __float2bfloat16_rn(he.x - __bfloat162float(h0));
                __nv_bfloat16 l1 = __float2bfloat16_rn(he.y - __bfloat162float(h1));
                *(__nv_bfloat162*)&g_hh[b * DIM + d] = __nv_bfloat162(h0, h1);
                *(__nv_bfloat162*)&g_hl[b * DIM + d] = __nv_bfloat162(l0, l1);
            }
        }
        grid_barrier(&s_epoch, t == T_STEPS - 1);
    }
}

// ---------------------------------------------------------------------------
extern "C" void kernel_launch(void* const* d_in, const int* in_sizes, int n_in,
                              void* d_out, int out_size) {
    const float* ins        = (const float*)d_in[0];
    const float* hiddens    = (const float*)d_in[1];
    const void*  dones      = d_in[2];
    const float* init_carry = (const float*)d_in[3];
    const float* W_i        = (const float*)d_in[4];
    const float* W_h        = (const float*)d_in[5];
    const float* b_i        = (const float*)d_in[6];
    const float* b_hn       = (const float*)d_in[7];
    float* out = (float*)d_out;

    // runtime __device__ global addresses for convert kernel args
    __nv_bfloat16 *wi_hi_p, *wi_lo_p, *wh_hi_p, *wh_lo_p;
    cudaGetSymbolAddress((void**)&wi_hi_p, g_wi_hi);
    cudaGetSymbolAddress((void**)&wi_lo_p, g_wi_lo);
    cudaGetSymbolAddress((void**)&wh_hi_p, g_wh_hi);
    cudaGetSymbolAddress((void**)&wh_lo_p, g_wh_lo);

    cudaFuncSetAttribute(scan_kernel,
                         cudaFuncAttributeMaxDynamicSharedMemorySize, SCAN_SMEM);

    detect_dones_kernel<<<1, 1>>>((const unsigned char*)dones);

    // bf16 hi/lo splits
    convert_ins_kernel<<<(int)(((size_t)M_TOTAL * DIM / 4) / 256), 256>>>(ins);
    {
        dim3 gw(N3 / 32, DIM / 32);       // (96, 32)
        convert_w_kernel<<<gw, 256>>>(W_i, wi_hi_p, wi_lo_p);
        convert_w_kernel<<<gw, 256>>>(W_h, wh_hi_p, wh_lo_p);
    }

    // HMMA xproj
    {
        dim3 grid(N3 / 128, M_TOTAL / 128);   // (24, 128)
        gemm_xproj_mma_kernel<<<grid, 256>>>(b_i);
    }

    // persistent HMMA scan
    scan_kernel<<<NCTA, NTHR, SCAN_SMEM>>>(hiddens, dones, init_carry, b_hn, out);
}